// round 9
// baseline (speedup 1.0000x reference)
#include <cuda_runtime.h>
#include <cuda_bf16.h>

#define Nn 22
#define Fd 192
#define NB4 4
#define MR 96
#define THREADS 512

typedef unsigned int u32;
typedef unsigned long long u64;
typedef unsigned short u16;

// ---- SMEM layout (bytes) ----
#define OFF_ADJ 0                 // 484 f
#define OFF_AVS 1952              // 1152 f (a1,a2,ao)
#define OFF_A   6656
#define ASTR    400               // 96 rows x 192 bf16
#define OFF_AHI OFF_A
#define OFF_ALO (OFF_A + 38400)   // 45056
#define OFF_B   83456             // dbuf: per buf hi plane 15360 + lo plane 15360
#define BSTR    80                // 192 rows x 32 bf16
#define BPL     15360
#define BBUF    30720
#define OFF_WS  (OFF_B + BBUF)    // overlays buf1 (dead during attention phases)
#define WSB     1056              // floats per batch: ev 44 + attw_dup 1012
#define OFF_WHS 144896            // 96 x 194 fp32
#define WS_S    194
#define SMEM_TOTAL 219392

// ---- device-global weight splits (sanctioned scratch) ----
static __device__ __nv_bfloat16 g_w12t_hi[384*192];
static __device__ __nv_bfloat16 g_w12t_lo[384*192];
static __device__ __nv_bfloat16 g_wot_hi[192*384];
static __device__ __nv_bfloat16 g_wot_lo[192*384];

// ---- helpers ----
__device__ __forceinline__ u32 smem_u32(const void* p){
    u32 a;
    asm("{ .reg .u64 t; cvta.to.shared.u64 t, %1; cvt.u32.u64 %0, t; }" : "=r"(a) : "l"(p));
    return a;
}
__device__ __forceinline__ void split_bf16(float v, u16& h, u16& l){
    __nv_bfloat16 hb = __float2bfloat16(v);
    float hf = __bfloat162float(hb);
    __nv_bfloat16 lb = __float2bfloat16(v - hf);
    h = __bfloat16_as_ushort(hb);
    l = __bfloat16_as_ushort(lb);
}
__device__ __forceinline__ float elu1(float v){ return (v > 0.0f) ? v : (__expf(v) - 1.0f); }

__device__ __forceinline__ void unpack2(u64 v, float& lo, float& hi) {
    asm("mov.b64 {%0, %1}, %2;" : "=f"(lo), "=f"(hi) : "l"(v));
}
__device__ __forceinline__ void fma2(u64& d, u64 a, u64 b) {
    asm("fma.rn.f32x2 %0, %1, %2, %0;" : "+l"(d) : "l"(a), "l"(b));
}

#define CPA16(sa, g) asm volatile("cp.async.cg.shared.global [%0], [%1], 16;" :: "r"((u32)(sa)), "l"(g) : "memory")
#define CPC()  asm volatile("cp.async.commit_group;" ::: "memory")
#define CPW1() asm volatile("cp.async.wait_group 1;" ::: "memory")
#define CPW0() asm volatile("cp.async.wait_group 0;" ::: "memory")

__device__ __forceinline__ void mma_bf16(float* c, const u32* a, u32 b0, u32 b1){
    asm volatile("mma.sync.aligned.m16n8k16.row.col.f32.bf16.bf16.f32 "
        "{%0,%1,%2,%3}, {%4,%5,%6,%7}, {%8,%9}, {%0,%1,%2,%3};"
        : "+f"(c[0]),"+f"(c[1]),"+f"(c[2]),"+f"(c[3])
        : "r"(a[0]),"r"(a[1]),"r"(a[2]),"r"(a[3]),"r"(b0),"r"(b1));
}
__device__ __forceinline__ void ldsm4(u32 a, u32* r){
    asm volatile("ldmatrix.sync.aligned.m8n8.x4.shared.b16 {%0,%1,%2,%3}, [%4];"
        : "=r"(r[0]),"=r"(r[1]),"=r"(r[2]),"=r"(r[3]) : "r"(a));
}
__device__ __forceinline__ void ldsm2(u32 a, u32* r){
    asm volatile("ldmatrix.sync.aligned.m8n8.x2.shared.b16 {%0,%1}, [%2];"
        : "=r"(r[0]),"=r"(r[1]) : "r"(a));
}

// softmax over 22 nodes; lane i handles row i; writes DUPLICATED pairs for f32x2
__device__ __forceinline__ void warp_softmax_dup(const float* __restrict__ ev, const float* __restrict__ adjs,
                                                 float* __restrict__ attwd, int lane)
{
    if (lane < Nn) {
        int i = lane;
        float esrc = ev[i];
        float vals[Nn];
        float mx = -1e30f;
#pragma unroll
        for (int j = 0; j < Nn; j++) {
            if (adjs[i * Nn + j] != 0.0f) {
                float v = esrc + ev[Nn + j];
                v = (v > 0.0f) ? v : 0.2f * v;
                vals[j] = v;
                mx = fmaxf(mx, v);
            } else vals[j] = -1e30f;
        }
        float ssum = 0.0f;
#pragma unroll
        for (int j = 0; j < Nn; j++) {
            float e = (vals[j] > -1e29f) ? __expf(vals[j] - mx) : 0.0f;
            vals[j] = e; ssum += e;
        }
        float inv = 1.0f / ssum;
#pragma unroll
        for (int j = 0; j < Nn; j++) {
            float vv = vals[j] * inv;
            attwd[(i * 23 + j) * 2]     = vv;
            attwd[(i * 23 + j) * 2 + 1] = vv;
        }
    }
}

// stream one B chunk: 192 n-rows x 32 k (hi+lo) via cp.async 16B
__device__ __forceinline__ void issue_b(u32 dst, const __nv_bfloat16* gh, const __nv_bfloat16* gl,
                                        int tid, int rs)
{
#pragma unroll
    for (int q = 0; q < 3; q++) {
        int lin = tid + THREADS * q;        // 0..1535
        int plane = lin / 768;
        int rem = lin - plane * 768;
        int row = rem >> 2, piece = rem & 3;
        const __nv_bfloat16* src = (plane ? gl : gh) + row * rs + piece * 8;
        CPA16(dst + plane * BPL + row * BSTR + piece * 16, src);
    }
}

// GEMM mainloop over 6 k-chunks; caller MUST have issued chunk0 into buf0 (+CPC)
__device__ __forceinline__ void gemm6(u32 sb, float acc[3][3][4],
                                      const __nv_bfloat16* bh0, const __nv_bfloat16* bl0, int rs,
                                      int tid, int wm, int wn, int lane)
{
    const u32 laneA = (u32)((lane & 15) * ASTR + (lane >> 4) * 16);
    const u32 laneB = (u32)((lane & 7) * BSTR + ((lane >> 3) & 1) * 16);
    const u32 Abase = sb + OFF_AHI + wm * 48 * ASTR + laneA;
    const u32 Bbase = sb + OFF_B + wn * 24 * BSTR + laneB;

    for (int kc = 0; kc < 6; kc++) {
        int buf = kc & 1;
        __syncthreads();
        if (kc < 5) {
            issue_b(sb + OFF_B + (buf ^ 1) * BBUF, bh0 + (kc + 1) * 32, bl0 + (kc + 1) * 32, tid, rs);
            CPC(); CPW1();
        } else CPW0();
        __syncthreads();

        const u32 Ah = Abase + kc * 64;
        const u32 Bh = Bbase + buf * BBUF;
#pragma unroll
        for (int s = 0; s < 2; s++) {
            u32 ah[3][4], al[3][4], bh[3][2], bl[3][2];
#pragma unroll
            for (int mt = 0; mt < 3; mt++) {
                ldsm4(Ah + mt * 16 * ASTR + s * 32, ah[mt]);
                ldsm4(Ah + 38400 + mt * 16 * ASTR + s * 32, al[mt]);
            }
#pragma unroll
            for (int t = 0; t < 3; t++) {
                ldsm2(Bh + t * 8 * BSTR + s * 32, bh[t]);
                ldsm2(Bh + BPL + t * 8 * BSTR + s * 32, bl[t]);
            }
#pragma unroll
            for (int mt = 0; mt < 3; mt++)
#pragma unroll
                for (int t = 0; t < 3; t++) {
                    mma_bf16(acc[mt][t], ah[mt], bh[t][0], bh[t][1]);
                    mma_bf16(acc[mt][t], ah[mt], bl[t][0], bl[t][1]);
                    mma_bf16(acc[mt][t], al[mt], bh[t][0], bh[t][1]);
                }
        }
    }
}

// ================= prep =================
__global__ void k_prep(const float* __restrict__ W1, const float* __restrict__ W2,
                       const float* __restrict__ Wo)
{
    int idx = blockIdx.x * blockDim.x + threadIdx.x;
    if (idx < 384 * 192) {
        int n = idx / 192, k = idx % 192;
        float v = (n < 192) ? W1[k * 192 + n] : W2[k * 192 + (n - 192)];
        u16 h, l; split_bf16(v, h, l);
        g_w12t_hi[idx] = __ushort_as_bfloat16(h);
        g_w12t_lo[idx] = __ushort_as_bfloat16(l);
    } else if (idx < 2 * 384 * 192) {
        int j = idx - 384 * 192;
        int n = j / 384, k = j % 384;
        float v = Wo[k * 192 + n];
        u16 h, l; split_bf16(v, h, l);
        g_wot_hi[j] = __ushort_as_bfloat16(h);
        g_wot_lo[j] = __ushort_as_bfloat16(l);
    }
}

// ================= fused kernel =================
__global__ __launch_bounds__(THREADS, 1)
void k_fused(const float* __restrict__ x, const float* __restrict__ adj,
             const float* __restrict__ a1, const float* __restrict__ a2,
             const float* __restrict__ ao, float* __restrict__ out, int nbatch)
{
    extern __shared__ char smc[];
    float* smf = (float*)smc;
    const u32 sb = smem_u32(smc);
    const int tid = threadIdx.x, wid = tid >> 5, lane = tid & 31;
    const int l4 = lane >> 2, lq = lane & 3;
    const int wm = wid & 1, wn = wid >> 1;       // GEMM roles: 2M x 8N
    const int wb = wid >> 2, q = wid & 3;        // attention roles: 4 batches x 4 slices
    const int b0 = blockIdx.x * NB4;
    const int nb = min(NB4, nbatch - b0);
    const int nrows = nb * Nn;
    const long long row0 = (long long)b0 * Nn;

    float* adjs = smf + OFF_ADJ / 4;
    float* avs  = smf + OFF_AVS / 4;
    float* whs  = (float*)(smc + OFF_WHS);       // Wh per head; later who

    // prefetch GEMM1-h0 chunk0 before anything else
    issue_b(sb + OFF_B, g_w12t_hi, g_w12t_lo, tid, 192);
    CPC();

    for (int i = tid; i < Nn * Nn; i += THREADS) adjs[i] = adj[i];
    for (int i = tid; i < 1152; i += THREADS)
        avs[i] = (i < 384) ? a1[i] : (i < 768 ? a2[i - 384] : ao[i - 768]);

    // A = split(x): 96 rows x 192 (pad rows zeroed)
    for (int idx = tid; idx < MR * 96; idx += THREADS) {
        int r = idx / 96, kp = idx % 96;
        float2 v = make_float2(0.f, 0.f);
        if (r < nrows) v = *(const float2*)(x + (row0 + r) * Fd + kp * 2);
        u16 h0,l0,h1,l1;
        split_bf16(v.x, h0, l0); split_bf16(v.y, h1, l1);
        *(u32*)(smc + OFF_AHI + r * ASTR + kp * 4) = h0 | ((u32)h1 << 16);
        *(u32*)(smc + OFF_ALO + r * ASTR + kp * 4) = l0 | ((u32)l1 << 16);
    }

    // GEMM2 accumulators persist across both k-halves
    float acc2[3][3][4];
#pragma unroll
    for (int mt = 0; mt < 3; mt++)
#pragma unroll
        for (int nt = 0; nt < 3; nt++)
#pragma unroll
            for (int p = 0; p < 4; p++) acc2[mt][nt][p] = 0.0f;

    for (int h = 0; h < 2; h++) {
        // ---- GEMM1 head h ----
        {
            float acc[3][3][4];
#pragma unroll
            for (int mt = 0; mt < 3; mt++)
#pragma unroll
                for (int nt = 0; nt < 3; nt++)
#pragma unroll
                    for (int p = 0; p < 4; p++) acc[mt][nt][p] = 0.0f;

            gemm6(sb, acc, g_w12t_hi + h * 192 * 192, g_w12t_lo + h * 192 * 192, 192,
                  tid, wm, wn, lane);

            __syncthreads();
#pragma unroll
            for (int mt = 0; mt < 3; mt++)
#pragma unroll
                for (int nt = 0; nt < 3; nt++) {
                    int r = wm * 48 + mt * 16 + l4, c = wn * 24 + nt * 8 + lq * 2;
                    whs[r * WS_S + c]           = acc[mt][nt][0];
                    whs[r * WS_S + c + 1]       = acc[mt][nt][1];
                    whs[(r + 8) * WS_S + c]     = acc[mt][nt][2];
                    whs[(r + 8) * WS_S + c + 1] = acc[mt][nt][3];
                }
        }
        // prefetch GEMM2-h chunk0 into buf0 (buf0 free; attention uses buf1 overlay)
        issue_b(sb + OFF_B, g_wot_hi + h * 192, g_wot_lo + h * 192, tid, 384);
        CPC();
        __syncthreads();

        // ---- attention head h (packed f32x2); hc written split into A planes ----
        float* ev    = smf + OFF_WS / 4 + wb * WSB;
        float* attwd = ev + 44;
        {
            const int sd = q >> 1, i0 = (q & 1) * 11;
            const float* av = avs + h * 384 + sd * 192;
            for (int i = i0; i < i0 + 11; i++) {
                const float* rw = whs + (wb * Nn + i) * WS_S;
                u64 s2 = 0;
#pragma unroll
                for (int j = 0; j < 3; j++)
                    fma2(s2, *(const u64*)(rw + lane * 2 + 64 * j),
                             *(const u64*)(av + lane * 2 + 64 * j));
                float slo, shi; unpack2(s2, slo, shi);
                float s = slo + shi;
#pragma unroll
                for (int o = 16; o; o >>= 1) s += __shfl_xor_sync(0xffffffffu, s, o);
                if (lane == 0) ev[sd * Nn + i] = s;
            }
        }
        __syncthreads();
        if (q == 0) warp_softmax_dup(ev, adjs, attwd, lane);
        __syncthreads();
        if (lane < 24) {
            int c = q * 48 + lane * 2;
            u64 wv[Nn];
#pragma unroll
            for (int j = 0; j < Nn; j++)
                wv[j] = *(const u64*)(whs + (wb * Nn + j) * WS_S + c);
#pragma unroll 2
            for (int i = 0; i < Nn; i++) {
                u64 a2p = 0;
                const float* awd = attwd + i * 46;
#pragma unroll
                for (int j = 0; j < Nn; j++)
                    fma2(a2p, wv[j], *(const u64*)(awd + 2 * j));
                float sx, sy; unpack2(a2p, sx, sy);
                sx = elu1(sx); sy = elu1(sy);
                u16 h0,l0,h1,l1;
                split_bf16(sx, h0, l0); split_bf16(sy, h1, l1);
                int rr = wb * Nn + i;
                *(u32*)(smc + OFF_AHI + rr * ASTR + c * 2) = h0 | ((u32)h1 << 16);
                *(u32*)(smc + OFF_ALO + rr * ASTR + c * 2) = l0 | ((u32)l1 << 16);
            }
        }
        // gemm6's first sync orders hc writes before A reads

        // ---- GEMM2 partial: k-half h ----
        gemm6(sb, acc2, g_wot_hi + h * 192, g_wot_lo + h * 192, 384,
              tid, wm, wn, lane);

        if (h == 0) {
            // prefetch GEMM1-h1 chunk0; then reload+split x into A planes
            issue_b(sb + OFF_B, g_w12t_hi + 192 * 192, g_w12t_lo + 192 * 192, tid, 192);
            CPC();
            __syncthreads();   // all warps done reading A (GEMM2-h0)
            for (int idx = tid; idx < MR * 96; idx += THREADS) {
                int r = idx / 96, kp = idx % 96;
                float2 v = make_float2(0.f, 0.f);
                if (r < nrows) v = *(const float2*)(x + (row0 + r) * Fd + kp * 2);
                u16 h0,l0,h1,l1;
                split_bf16(v.x, h0, l0); split_bf16(v.y, h1, l1);
                *(u32*)(smc + OFF_AHI + r * ASTR + kp * 4) = h0 | ((u32)h1 << 16);
                *(u32*)(smc + OFF_ALO + r * ASTR + kp * 4) = l0 | ((u32)l1 << 16);
            }
        }
    }

    // ---- epilogue: acc2 -> who (whs region) ----
    __syncthreads();
#pragma unroll
    for (int mt = 0; mt < 3; mt++)
#pragma unroll
        for (int nt = 0; nt < 3; nt++) {
            int r = wm * 48 + mt * 16 + l4, c = wn * 24 + nt * 8 + lq * 2;
            whs[r * WS_S + c]           = acc2[mt][nt][0];
            whs[r * WS_S + c + 1]       = acc2[mt][nt][1];
            whs[(r + 8) * WS_S + c]     = acc2[mt][nt][2];
            whs[(r + 8) * WS_S + c + 1] = acc2[mt][nt][3];
        }
    __syncthreads();

    // ---- output attention (packed) + elu + residual ----
    float* ev    = smf + OFF_WS / 4 + wb * WSB;
    float* attwd = ev + 44;
    {
        const int sd = q >> 1, i0 = (q & 1) * 11;
        const float* av = avs + 768 + sd * 192;
        for (int i = i0; i < i0 + 11; i++) {
            const float* rw = whs + (wb * Nn + i) * WS_S;
            u64 s2 = 0;
#pragma unroll
            for (int j = 0; j < 3; j++)
                fma2(s2, *(const u64*)(rw + lane * 2 + 64 * j),
                         *(const u64*)(av + lane * 2 + 64 * j));
            float slo, shi; unpack2(s2, slo, shi);
            float s = slo + shi;
#pragma unroll
            for (int o = 16; o; o >>= 1) s += __shfl_xor_sync(0xffffffffu, s, o);
            if (lane == 0) ev[sd * Nn + i] = s;
        }
    }
    __syncthreads();
    if (q == 0) warp_softmax_dup(ev, adjs, attwd, lane);
    __syncthreads();
    if (wb < nb && lane < 24) {
        int c = q * 48 + lane * 2;
        u64 wv[Nn];
#pragma unroll
        for (int j = 0; j < Nn; j++)
            wv[j] = *(const u64*)(whs + (wb * Nn + j) * WS_S + c);
#pragma unroll 2
        for (int i = 0; i < Nn; i++) {
            u64 a2p = 0;
            const float* awd = attwd + i * 46;
#pragma unroll
            for (int j = 0; j < Nn; j++)
                fma2(a2p, wv[j], *(const u64*)(awd + 2 * j));
            float sx, sy; unpack2(a2p, sx, sy);
            long long gi = (row0 + wb * Nn + i) * Fd + c;
            float2 xr = *(const float2*)(x + gi);
            float2 o;
            o.x = elu1(sx) + xr.x;
            o.y = elu1(sy) + xr.y;
            *(float2*)(out + gi) = o;
        }
    }
}

extern "C" void kernel_launch(void* const* d_in, const int* in_sizes, int n_in,
                              void* d_out, int out_size)
{
    const float* x   = (const float*)d_in[0];
    const float* adj = (const float*)d_in[1];
    const float* W1  = (const float*)d_in[2];
    const float* a1  = (const float*)d_in[3];
    const float* W2  = (const float*)d_in[4];
    const float* a2  = (const float*)d_in[5];
    const float* Wo  = (const float*)d_in[6];
    const float* ao  = (const float*)d_in[7];
    float* out = (float*)d_out;

    int nbatch = in_sizes[0] / (Nn * Fd);
    int ctas = (nbatch + NB4 - 1) / NB4;

    cudaFuncSetAttribute(k_fused, cudaFuncAttributeMaxDynamicSharedMemorySize, SMEM_TOTAL);

    k_prep<<<(2 * 384 * 192 + 255) / 256, 256>>>(W1, W2, Wo);
    k_fused<<<ctas, THREADS, SMEM_TOTAL>>>(x, adj, a1, a2, ao, out, nbatch);
}